// round 13
// baseline (speedup 1.0000x reference)
#include <cuda_runtime.h>
#include <cuda_bf16.h>
#include <mma.h>
#include <math_constants.h>
#include <cstdint>
using namespace nvcuda;

#define BDIM 2048
#define EDIM 512
#define CDIM 16384
#define PCOLS 256              // per-row LSE partials: CDIM/64

// ---------------- scratch (static device arrays; no allocation) ----------------
__device__ __nv_bfloat16 g_w[(size_t)CDIM * EDIM];     // 16 MiB
__device__ __nv_bfloat16 g_xb[(size_t)BDIM * EDIM];    // 2 MiB
__device__ __nv_bfloat16 g_tb[(size_t)BDIM * EDIM];    // 2 MiB
__device__ float g_sim[(size_t)BDIM * BDIM];           // 16 MiB
__device__ float g_tsim[(size_t)BDIM * BDIM];          // 16 MiB
__device__ float g_pmax[(size_t)BDIM * PCOLS];         // 2 MiB
__device__ float g_psum[(size_t)BDIM * PCOLS];         // 2 MiB
__device__ float g_rank_row[BDIM];
__device__ float g_kd_row[BDIM];
__device__ int   g_labels[BDIM];
__device__ unsigned int g_done;          // reset each call in prep_kernel

// ---------------- block-wide reduction (op=0 sum, op=1 max) ----------------
__device__ __forceinline__ float blkred(float v, int op) {
    __shared__ float tmp[32];
    int lane = threadIdx.x & 31, w = threadIdx.x >> 5;
#pragma unroll
    for (int o = 16; o > 0; o >>= 1) {
        float u = __shfl_xor_sync(0xffffffffu, v, o);
        v = op ? fmaxf(v, u) : v + u;
    }
    __syncthreads();
    if (lane == 0) tmp[w] = v;
    __syncthreads();
    int nw = blockDim.x >> 5;
    if (w == 0) {
        v = (lane < nw) ? tmp[lane] : (op ? -CUDART_INF_F : 0.f);
#pragma unroll
        for (int o = 16; o > 0; o >>= 1) {
            float u = __shfl_xor_sync(0xffffffffu, v, o);
            v = op ? fmaxf(v, u) : v + u;
        }
        if (lane == 0) tmp[0] = v;
    }
    __syncthreads();
    return tmp[0];
}

// ---------------- fused prep: normalize_w | cast | labels (one launch) ----------------
#define NORM_BLOCKS (CDIM / 4)                // 4096
#define CAST_BLOCKS 1024                      // 128 thr x 2 float4 per tensor
#define NPREP_TOTAL (NORM_BLOCKS + CAST_BLOCKS + 1)

__global__ void __launch_bounds__(128) prep_kernel(const float* __restrict__ cm,
                                                   const float* __restrict__ x,
                                                   const float* __restrict__ t,
                                                   const void* __restrict__ lp) {
    int bid = blockIdx.x, tid = threadIdx.x;
    int lane = tid & 31, warp = tid >> 5;
    if (bid < NORM_BLOCKS) {
        int row = bid * 4 + warp;
        const float4* src = reinterpret_cast<const float4*>(cm) + (size_t)row * (EDIM / 4);
        float4 v[4];
#pragma unroll
        for (int q = 0; q < 4; q++) v[q] = src[lane + 32 * q];
        float ss = 0.f;
#pragma unroll
        for (int q = 0; q < 4; q++)
            ss += v[q].x * v[q].x + v[q].y * v[q].y + v[q].z * v[q].z + v[q].w * v[q].w;
#pragma unroll
        for (int o = 16; o > 0; o >>= 1) ss += __shfl_xor_sync(0xffffffffu, ss, o);
        float r = rsqrtf(ss);
        uint2* dstrow = reinterpret_cast<uint2*>(g_w + (size_t)row * EDIM);
#pragma unroll
        for (int q = 0; q < 4; q++) {
            __nv_bfloat162 lo = __floats2bfloat162_rn(v[q].x * r, v[q].y * r);
            __nv_bfloat162 hi = __floats2bfloat162_rn(v[q].z * r, v[q].w * r);
            uint2 u;
            u.x = *reinterpret_cast<uint32_t*>(&lo);
            u.y = *reinterpret_cast<uint32_t*>(&hi);
            dstrow[lane + 32 * q] = u;
        }
    } else if (bid < NORM_BLOCKS + CAST_BLOCKS) {
        int base = (bid - NORM_BLOCKS) * 256 + tid;   // float4 index, stride grid
        const float4* x4 = reinterpret_cast<const float4*>(x);
        const float4* t4 = reinterpret_cast<const float4*>(t);
        uint2* xb2 = reinterpret_cast<uint2*>(g_xb);
        uint2* tb2 = reinterpret_cast<uint2*>(g_tb);
#pragma unroll
        for (int p = 0; p < 2; p++) {
            int i = base + p * 128;                    // 262144 float4 total
            float4 a = x4[i], b = t4[i];
            __nv_bfloat162 a0 = __floats2bfloat162_rn(a.x, a.y);
            __nv_bfloat162 a1 = __floats2bfloat162_rn(a.z, a.w);
            __nv_bfloat162 b0 = __floats2bfloat162_rn(b.x, b.y);
            __nv_bfloat162 b1 = __floats2bfloat162_rn(b.z, b.w);
            uint2 ua, ub;
            ua.x = *reinterpret_cast<uint32_t*>(&a0);
            ua.y = *reinterpret_cast<uint32_t*>(&a1);
            ub.x = *reinterpret_cast<uint32_t*>(&b0);
            ub.y = *reinterpret_cast<uint32_t*>(&b1);
            xb2[i] = ua;
            tb2[i] = ub;
        }
    } else {
        __shared__ int is32;
        const long long* l64 = (const long long*)lp;
        const int* l32 = (const int*)lp;
        if (tid == 0) { is32 = 0; g_done = 0u; }   // reset finalize counter
        __syncthreads();
        for (int i = tid; i < 1024; i += 128) {
            long long v = l64[i];
            if (v < 0 || v >= 256) is32 = 1;
        }
        __syncthreads();
        int f = is32;
        for (int i = tid; i < BDIM; i += 128)
            g_labels[i] = f ? l32[i] : (int)l64[i];
    }
}

// =============== fused bf16 GEMM: C[m,n] = sum_k A[m,k]*B[n,k] ===============
// Tile space (2320): [0,2048) logits tiles w/ fused LSE partials;
//                    [2048,2320) symmetric Gram upper-tri tiles (+mirror store).
// Grid = 2220 CTAs (5 full waves at 3 CTAs/SM x 148 SMs); CTAs 0..99 process
// two tiles (their own + tile 2220+bid) to absorb the fractional 6th wave.
#define BM 128
#define BN 128
#define BK 64
#define KSTR (BK + 8)          // 72 bf16 = 144B row stride (16B multiple)
#define NSTAGE (EDIM / BK)     // 8
#define TILE_ELEMS (BM * KSTR) // 9216 bf16 per tile buffer
#define TILE_BYTES (TILE_ELEMS * 2)
#define DYNB (4 * TILE_BYTES)  // A0,A1,B0,B1 = 73728 B
#define NPAIR 136              // 16*17/2 upper-tri 128x128 tiles of 2048x2048
#define NLOGIT 2048
#define NTILES (NLOGIT + 2 * NPAIR)   // 2320
#define NCTA 2220
#define NDOUBLE (NTILES - NCTA)       // 100

__device__ __forceinline__ void cp16(uint32_t s, const void* g) {
    asm volatile("cp.async.cg.shared.global [%0], [%1], 16;\n" :: "r"(s), "l"(g));
}
__device__ __forceinline__ void cp_commit() {
    asm volatile("cp.async.commit_group;\n");
}
template <int N>
__device__ __forceinline__ void cp_wait() {
    asm volatile("cp.async.wait_group %0;\n" :: "n"(N));
}

__global__ void __launch_bounds__(128, 3) fused_gemm_kernel() {
    extern __shared__ __nv_bfloat16 dyn[];  // [A0 A1 B0 B1]

    int tid = threadIdx.x;
    int wid = tid >> 5, lane = tid & 31;
    int wr = wid >> 1, wc = wid & 1;        // 2x2 warps, each 64x64
    int lr0 = tid >> 3, lc0 = tid & 7;
    uint32_t dynb = (uint32_t)__cvta_generic_to_shared(dyn);
    uint32_t sSt = (uint32_t)((lr0 * KSTR + lc0 * 8) * 2);

    int nwork = (blockIdx.x < NDOUBLE) ? 2 : 1;
    for (int w = 0; w < nwork; w++) {
        int tile = (w == 0) ? blockIdx.x : (NCTA + blockIdx.x);
        if (w > 0) __syncthreads();   // protect dyn reuse across tiles

        const __nv_bfloat16 *A, *B;
        float* dst = nullptr;
        int m0, n0, mode, nt = 0, bx = 0, by = 0;
        if (tile < NLOGIT) {
            mode = 0;
            nt = tile & 127;
            m0 = (tile >> 7) * BM;
            n0 = nt * BN;
            A = g_xb; B = g_w;
        } else {
            mode = 1;
            int g = tile - NLOGIT;
            int which = (g >= NPAIR) ? 1 : 0;
            int pair = g - which * NPAIR;
            bx = (int)((sqrtf(8.f * pair + 1.f) - 1.f) * 0.5f);
            if (bx * (bx + 1) / 2 > pair) bx--;
            if ((bx + 1) * (bx + 2) / 2 <= pair) bx++;
            by = pair - bx * (bx + 1) / 2;       // by <= bx
            m0 = by * BM;
            n0 = bx * BN;
            A = which ? g_tb : g_xb;
            B = A;
            dst = which ? g_tsim : g_sim;
        }

        const __nv_bfloat16* Ga = A + (size_t)m0 * EDIM;
        const __nv_bfloat16* Gb = B + (size_t)n0 * EDIM;

        wmma::fragment<wmma::accumulator, 16, 16, 16, float> acc[4][4];
#pragma unroll
        for (int i = 0; i < 4; i++)
#pragma unroll
            for (int j = 0; j < 4; j++) wmma::fill_fragment(acc[i][j], 0.f);

        // prefetch stage 0
        {
            uint32_t ab = dynb, bb = dynb + 2 * TILE_BYTES;
#pragma unroll
            for (int it = 0; it < 8; it++) {
                int r = lr0 + it * 16;
                cp16(ab + sSt + it * 16 * KSTR * 2, Ga + (size_t)r * EDIM + lc0 * 8);
                cp16(bb + sSt + it * 16 * KSTR * 2, Gb + (size_t)r * EDIM + lc0 * 8);
            }
            cp_commit();
        }

        for (int s = 0; s < NSTAGE; s++) {
            if (s + 1 < NSTAGE) {
                int nb = (s + 1) & 1;
                uint32_t ab = dynb + nb * TILE_BYTES;
                uint32_t bb = dynb + (2 + nb) * TILE_BYTES;
                const __nv_bfloat16* pA = Ga + (s + 1) * BK + lc0 * 8;
                const __nv_bfloat16* pB = Gb + (s + 1) * BK + lc0 * 8;
#pragma unroll
                for (int it = 0; it < 8; it++) {
                    int r = lr0 + it * 16;
                    cp16(ab + sSt + it * 16 * KSTR * 2, pA + (size_t)r * EDIM);
                    cp16(bb + sSt + it * 16 * KSTR * 2, pB + (size_t)r * EDIM);
                }
                cp_commit();
                cp_wait<1>();
            } else {
                cp_wait<0>();
            }
            __syncthreads();

            const __nv_bfloat16* cA = dyn + (s & 1) * TILE_ELEMS;
            const __nv_bfloat16* cB = dyn + (2 + (s & 1)) * TILE_ELEMS;
#pragma unroll
            for (int kk = 0; kk < BK; kk += 16) {
                wmma::fragment<wmma::matrix_a, 16, 16, 16, __nv_bfloat16, wmma::row_major> fa[4];
                wmma::fragment<wmma::matrix_b, 16, 16, 16, __nv_bfloat16, wmma::col_major> fb[4];
#pragma unroll
                for (int i = 0; i < 4; i++)
                    wmma::load_matrix_sync(fa[i], &cA[(wr * 64 + i * 16) * KSTR + kk], KSTR);
#pragma unroll
                for (int j = 0; j < 4; j++)
                    wmma::load_matrix_sync(fb[j], &cB[(wc * 64 + j * 16) * KSTR + kk], KSTR);
#pragma unroll
                for (int i = 0; i < 4; i++)
#pragma unroll
                    for (int j = 0; j < 4; j++)
                        wmma::mma_sync(acc[i][j], fa[i], fb[j], acc[i][j]);
            }
            __syncthreads();
        }

        if (mode == 0) {
            float* stage = (float*)dyn;
            float* stw = stage + wid * 16 * 68;
            int r = lane >> 1, half = lane & 1;
#pragma unroll
            for (int i = 0; i < 4; i++) {
#pragma unroll
                for (int j = 0; j < 4; j++)
                    wmma::store_matrix_sync(&stw[j * 16], acc[i][j], 68, wmma::mem_row_major);
                __syncwarp();
                float x[32];
#pragma unroll
                for (int q = 0; q < 32; q++) x[q] = stw[r * 68 + half * 32 + q] * 20.f;
                float M = x[0];
#pragma unroll
                for (int q = 1; q < 32; q++) M = fmaxf(M, x[q]);
                M = fmaxf(M, __shfl_xor_sync(0xffffffffu, M, 1));
                float s = 0.f;
#pragma unroll
                for (int q = 0; q < 32; q++) s += __expf(x[q] - M);
                s += __shfl_xor_sync(0xffffffffu, s, 1);
                if (half == 0) {
                    int grow = m0 + wr * 64 + i * 16 + r;
                    int pcol = nt * 2 + wc;
                    g_pmax[(size_t)grow * PCOLS + pcol] = M;
                    g_psum[(size_t)grow * PCOLS + pcol] = s;
                }
                __syncwarp();
            }
        } else {
#pragma unroll
            for (int i = 0; i < 4; i++)
#pragma unroll
                for (int j = 0; j < 4; j++)
                    wmma::store_matrix_sync(
                        &dst[(size_t)(m0 + wr * 64 + i * 16) * BDIM + n0 + wc * 64 + j * 16],
                        acc[i][j], BDIM, wmma::mem_row_major);
            if (bx != by) {
#pragma unroll
                for (int i = 0; i < 4; i++)
#pragma unroll
                    for (int j = 0; j < 4; j++)
                        wmma::store_matrix_sync(
                            &dst[(size_t)(n0 + wc * 64 + j * 16) * BDIM + m0 + wr * 64 + i * 16],
                            acc[i][j], BDIM, wmma::mem_col_major);
            }
        }
    }
}

// ======= fused per-row kernel: KD (2-pass KL) + LSE combine + target dot
//         + last-block finalize (no separate finalize launch) =======
// KL identity: kl = w/Zt + (Ms + ln Zs) - (Mt + ln Zt),
//   w = sum_j exp(b_j - Mt) * (b_j - a_j)
__global__ void __launch_bounds__(256) row_kernel(const int* __restrict__ epoch_p,
                                                  float* __restrict__ out, int out_size) {
    __shared__ float ssr[BDIM];       // scaled student row
    __shared__ float str[BDIM];       // scaled teacher row
    int row = blockIdx.x, tid = threadIdx.x;
    int li = g_labels[row];

    const float4* sr4 = (const float4*)(g_sim + (size_t)row * BDIM);
    const float4* tr4 = (const float4*)(g_tsim + (size_t)row * BDIM);
    const int4* lb4 = (const int4*)g_labels;
    float ms = -CUDART_INF_F, mt = -CUDART_INF_F;
#pragma unroll
    for (int it = 0; it < 2; it++) {
        int j4 = it * 256 + tid;          // float4 index 0..511
        int4 lv = lb4[j4];
        float4 a = sr4[j4], b = tr4[j4];
        float s0 = (lv.x == li) ? 0.25f : 0.125f;
        float s1 = (lv.y == li) ? 0.25f : 0.125f;
        float s2 = (lv.z == li) ? 0.25f : 0.125f;
        float s3 = (lv.w == li) ? 0.25f : 0.125f;
        a.x *= s0; a.y *= s1; a.z *= s2; a.w *= s3;
        b.x *= s0; b.y *= s1; b.z *= s2; b.w *= s3;
        *(float4*)&ssr[j4 * 4] = a;
        *(float4*)&str[j4 * 4] = b;
        ms = fmaxf(ms, fmaxf(fmaxf(a.x, a.y), fmaxf(a.z, a.w)));
        mt = fmaxf(mt, fmaxf(fmaxf(b.x, b.y), fmaxf(b.z, b.w)));
    }
    float Ms = blkred(ms, 1);
    float Mt = blkred(mt, 1);

    float zs = 0.f, zt = 0.f, wacc = 0.f;
#pragma unroll
    for (int it = 0; it < 2; it++) {
        int j4 = it * 256 + tid;
        float4 a = *(float4*)&ssr[j4 * 4];
        float4 b = *(float4*)&str[j4 * 4];
        zs += __expf(a.x - Ms) + __expf(a.y - Ms) + __expf(a.z - Ms) + __expf(a.w - Ms);
        float e0 = __expf(b.x - Mt), e1 = __expf(b.y - Mt);
        float e2 = __expf(b.z - Mt), e3 = __expf(b.w - Mt);
        zt += e0 + e1 + e2 + e3;
        wacc += e0 * (b.x - a.x) + e1 * (b.y - a.y) + e2 * (b.z - a.z) + e3 * (b.w - a.w);
    }
    float Zs = blkred(zs, 0);
    float Zt = blkred(zt, 0);
    float W  = blkred(wacc, 0);

    const __nv_bfloat16* xv = g_xb + (size_t)row * EDIM;
    const __nv_bfloat16* wv = g_w + (size_t)li * EDIM;
    float d = 0.f;
    for (int i = tid; i < EDIM; i += 256)
        d += __bfloat162float(xv[i]) * __bfloat162float(wv[i]);
    float tgt20 = blkred(d, 0) * 20.f;

    float pm = g_pmax[(size_t)row * PCOLS + tid];
    float pp = g_psum[(size_t)row * PCOLS + tid];
    float M = blkred(pm, 1);
    float S = blkred(pp * __expf(pm - M), 0);

    __shared__ int s_last;
    if (tid == 0) {
        g_kd_row[row] = W / Zt + (Ms + logf(Zs)) - (Mt + logf(Zt));
        g_rank_row[row] = logf(S) + M - tgt20;
        __threadfence();
        unsigned int prev = atomicAdd(&g_done, 1u);
        s_last = (prev == (unsigned int)(BDIM - 1)) ? 1 : 0;
    }
    __syncthreads();

    if (s_last) {
        __threadfence();
        float r = 0.f, k = 0.f;
        for (int i = tid; i < BDIM; i += 256) { r += g_rank_row[i]; k += g_kd_row[i]; }
        r = blkred(r, 0);
        k = blkred(k, 0);
        if (tid == 0) {
            float lr = r / (float)BDIM;
            float lk = k / (float)BDIM;
            int ei = *epoch_p;
            float ef = (ei >= 0 && ei < 10000000) ? (float)ei
                                                  : *reinterpret_cast<const float*>(epoch_p);
            float ramp = (ef / 150.f) * 16.0f;
            out[0] = lr + ramp * lk;
            if (out_size > 1) out[1] = lr;
            if (out_size > 2) out[2] = lk;
        }
    }
}

// ---------------- launch ----------------
extern "C" void kernel_launch(void* const* d_in, const int* in_sizes, int n_in,
                              void* d_out, int out_size) {
    const float* batch = (const float*)d_in[0];
    const float* teach = (const float*)d_in[1];
    const float* cmap  = (const float*)d_in[2];
    const void*  labels = d_in[3];
    const int*   epoch = (const int*)d_in[4];
    float* out = (float*)d_out;

    cudaFuncSetAttribute(fused_gemm_kernel,
                         cudaFuncAttributeMaxDynamicSharedMemorySize, DYNB);

    prep_kernel<<<NPREP_TOTAL, 128>>>(cmap, batch, teach, labels);
    fused_gemm_kernel<<<NCTA, 128, DYNB>>>();
    row_kernel<<<BDIM, 256>>>(epoch, out, out_size);
}

// round 14
// speedup vs baseline: 1.0471x; 1.0471x over previous
#include <cuda_runtime.h>
#include <cuda_bf16.h>
#include <mma.h>
#include <math_constants.h>
#include <cstdint>
using namespace nvcuda;

#define BDIM 2048
#define EDIM 512
#define CDIM 16384
#define PCOLS 256              // per-row LSE partials: CDIM/64

// ---------------- scratch (static device arrays; no allocation) ----------------
__device__ __nv_bfloat16 g_w[(size_t)CDIM * EDIM];     // 16 MiB
__device__ __nv_bfloat16 g_xb[(size_t)BDIM * EDIM];    // 2 MiB
__device__ __nv_bfloat16 g_tb[(size_t)BDIM * EDIM];    // 2 MiB
__device__ float g_sim[(size_t)BDIM * BDIM];           // 16 MiB
__device__ float g_tsim[(size_t)BDIM * BDIM];          // 16 MiB
__device__ float g_pmax[(size_t)BDIM * PCOLS];         // 2 MiB
__device__ float g_psum[(size_t)BDIM * PCOLS];         // 2 MiB
__device__ float g_rank_row[BDIM];
__device__ float g_kd_row[BDIM];
__device__ int   g_labels[BDIM];
__device__ unsigned int g_done;          // reset each call in prep_kernel

// ---------------- block-wide reduction (op=0 sum, op=1 max) ----------------
__device__ __forceinline__ float blkred(float v, int op) {
    __shared__ float tmp[32];
    int lane = threadIdx.x & 31, w = threadIdx.x >> 5;
#pragma unroll
    for (int o = 16; o > 0; o >>= 1) {
        float u = __shfl_xor_sync(0xffffffffu, v, o);
        v = op ? fmaxf(v, u) : v + u;
    }
    __syncthreads();
    if (lane == 0) tmp[w] = v;
    __syncthreads();
    int nw = blockDim.x >> 5;
    if (w == 0) {
        v = (lane < nw) ? tmp[lane] : (op ? -CUDART_INF_F : 0.f);
#pragma unroll
        for (int o = 16; o > 0; o >>= 1) {
            float u = __shfl_xor_sync(0xffffffffu, v, o);
            v = op ? fmaxf(v, u) : v + u;
        }
        if (lane == 0) tmp[0] = v;
    }
    __syncthreads();
    return tmp[0];
}

// ---------------- fused prep: normalize_w | cast | labels (one launch) ----------------
// norm: 8 rows per 128-thread block (2 rows per warp, loads batched, MLP=8)
// cast: 4 float4 per tensor per thread (MLP=8 across both tensors)
#define NORM_BLOCKS (CDIM / 8)                // 2048
#define CAST_BLOCKS 512
#define NPREP_TOTAL (NORM_BLOCKS + CAST_BLOCKS + 1)

__global__ void __launch_bounds__(128) prep_kernel(const float* __restrict__ cm,
                                                   const float* __restrict__ x,
                                                   const float* __restrict__ t,
                                                   const void* __restrict__ lp) {
    int bid = blockIdx.x, tid = threadIdx.x;
    int lane = tid & 31, warp = tid >> 5;
    if (bid < NORM_BLOCKS) {
        int row0 = bid * 8 + warp * 2;      // this warp handles rows row0, row0+1
        const float4* s0 = reinterpret_cast<const float4*>(cm) + (size_t)row0 * (EDIM / 4);
        const float4* s1 = s0 + (EDIM / 4);
        float4 v[8];
#pragma unroll
        for (int q = 0; q < 4; q++) v[q] = s0[lane + 32 * q];
#pragma unroll
        for (int q = 0; q < 4; q++) v[4 + q] = s1[lane + 32 * q];
        float ss0 = 0.f, ss1 = 0.f;
#pragma unroll
        for (int q = 0; q < 4; q++) {
            ss0 += v[q].x * v[q].x + v[q].y * v[q].y + v[q].z * v[q].z + v[q].w * v[q].w;
            ss1 += v[4 + q].x * v[4 + q].x + v[4 + q].y * v[4 + q].y
                 + v[4 + q].z * v[4 + q].z + v[4 + q].w * v[4 + q].w;
        }
#pragma unroll
        for (int o = 16; o > 0; o >>= 1) {
            ss0 += __shfl_xor_sync(0xffffffffu, ss0, o);
            ss1 += __shfl_xor_sync(0xffffffffu, ss1, o);
        }
        float r0 = rsqrtf(ss0), r1 = rsqrtf(ss1);
        uint2* d0 = reinterpret_cast<uint2*>(g_w + (size_t)row0 * EDIM);
        uint2* d1 = reinterpret_cast<uint2*>(g_w + (size_t)(row0 + 1) * EDIM);
#pragma unroll
        for (int q = 0; q < 4; q++) {
            __nv_bfloat162 lo = __floats2bfloat162_rn(v[q].x * r0, v[q].y * r0);
            __nv_bfloat162 hi = __floats2bfloat162_rn(v[q].z * r0, v[q].w * r0);
            uint2 u;
            u.x = *reinterpret_cast<uint32_t*>(&lo);
            u.y = *reinterpret_cast<uint32_t*>(&hi);
            d0[lane + 32 * q] = u;
        }
#pragma unroll
        for (int q = 0; q < 4; q++) {
            __nv_bfloat162 lo = __floats2bfloat162_rn(v[4 + q].x * r1, v[4 + q].y * r1);
            __nv_bfloat162 hi = __floats2bfloat162_rn(v[4 + q].z * r1, v[4 + q].w * r1);
            uint2 u;
            u.x = *reinterpret_cast<uint32_t*>(&lo);
            u.y = *reinterpret_cast<uint32_t*>(&hi);
            d1[lane + 32 * q] = u;
        }
    } else if (bid < NORM_BLOCKS + CAST_BLOCKS) {
        int base = (bid - NORM_BLOCKS) * 512 + tid;   // float4 index
        const float4* x4 = reinterpret_cast<const float4*>(x);
        const float4* t4 = reinterpret_cast<const float4*>(t);
        uint2* xb2 = reinterpret_cast<uint2*>(g_xb);
        uint2* tb2 = reinterpret_cast<uint2*>(g_tb);
        float4 a[4], b[4];
#pragma unroll
        for (int p = 0; p < 4; p++) {
            int i = base + p * 128;                    // 262144 float4 total
            a[p] = x4[i];
            b[p] = t4[i];
        }
#pragma unroll
        for (int p = 0; p < 4; p++) {
            int i = base + p * 128;
            __nv_bfloat162 a0 = __floats2bfloat162_rn(a[p].x, a[p].y);
            __nv_bfloat162 a1 = __floats2bfloat162_rn(a[p].z, a[p].w);
            __nv_bfloat162 b0 = __floats2bfloat162_rn(b[p].x, b[p].y);
            __nv_bfloat162 b1 = __floats2bfloat162_rn(b[p].z, b[p].w);
            uint2 ua, ub;
            ua.x = *reinterpret_cast<uint32_t*>(&a0);
            ua.y = *reinterpret_cast<uint32_t*>(&a1);
            ub.x = *reinterpret_cast<uint32_t*>(&b0);
            ub.y = *reinterpret_cast<uint32_t*>(&b1);
            xb2[i] = ua;
            tb2[i] = ub;
        }
    } else {
        __shared__ int is32;
        const long long* l64 = (const long long*)lp;
        const int* l32 = (const int*)lp;
        if (tid == 0) { is32 = 0; g_done = 0u; }   // reset finalize counter
        __syncthreads();
        for (int i = tid; i < 1024; i += 128) {
            long long v = l64[i];
            if (v < 0 || v >= 256) is32 = 1;
        }
        __syncthreads();
        int f = is32;
        for (int i = tid; i < BDIM; i += 128)
            g_labels[i] = f ? l32[i] : (int)l64[i];
    }
}

// =============== fused bf16 GEMM: C[m,n] = sum_k A[m,k]*B[n,k] ===============
// One launch: blocks [0,2048) = logits tiles w/ fused LSE partials;
//             blocks [2048,2320) = symmetric Gram upper-tri tiles (+mirror store).
#define BM 128
#define BN 128
#define BK 64
#define KSTR (BK + 8)          // 72 bf16 = 144B row stride (16B multiple)
#define NSTAGE (EDIM / BK)     // 8
#define TILE_ELEMS (BM * KSTR) // 9216 bf16 per tile buffer
#define TILE_BYTES (TILE_ELEMS * 2)
#define DYNB (4 * TILE_BYTES)  // A0,A1,B0,B1 = 73728 B
#define NPAIR 136              // 16*17/2 upper-tri 128x128 tiles of 2048x2048
#define NLOGIT 2048

__device__ __forceinline__ void cp16(uint32_t s, const void* g) {
    asm volatile("cp.async.cg.shared.global [%0], [%1], 16;\n" :: "r"(s), "l"(g));
}
__device__ __forceinline__ void cp_commit() {
    asm volatile("cp.async.commit_group;\n");
}
template <int N>
__device__ __forceinline__ void cp_wait() {
    asm volatile("cp.async.wait_group %0;\n" :: "n"(N));
}

__global__ void __launch_bounds__(128, 3) fused_gemm_kernel() {
    extern __shared__ __nv_bfloat16 dyn[];  // [A0 A1 B0 B1]

    int bid = blockIdx.x;
    int tid = threadIdx.x;
    int wid = tid >> 5, lane = tid & 31;
    int wr = wid >> 1, wc = wid & 1;        // 2x2 warps, each 64x64

    const __nv_bfloat16 *A, *B;
    float* dst = nullptr;
    int m0, n0, mode, nt = 0, bx = 0, by = 0;
    if (bid < NLOGIT) {
        mode = 0;
        nt = bid & 127;
        m0 = (bid >> 7) * BM;
        n0 = nt * BN;
        A = g_xb; B = g_w;
    } else {
        mode = 1;
        int g = bid - NLOGIT;
        int which = (g >= NPAIR) ? 1 : 0;
        int pair = g - which * NPAIR;
        bx = (int)((sqrtf(8.f * pair + 1.f) - 1.f) * 0.5f);
        if (bx * (bx + 1) / 2 > pair) bx--;
        if ((bx + 1) * (bx + 2) / 2 <= pair) bx++;
        by = pair - bx * (bx + 1) / 2;       // by <= bx
        m0 = by * BM;
        n0 = bx * BN;
        A = which ? g_tb : g_xb;
        B = A;
        dst = which ? g_tsim : g_sim;
    }

    uint32_t dynb = (uint32_t)__cvta_generic_to_shared(dyn);
    const __nv_bfloat16* Ga = A + (size_t)m0 * EDIM;
    const __nv_bfloat16* Gb = B + (size_t)n0 * EDIM;

    wmma::fragment<wmma::accumulator, 16, 16, 16, float> acc[4][4];
#pragma unroll
    for (int i = 0; i < 4; i++)
#pragma unroll
        for (int j = 0; j < 4; j++) wmma::fill_fragment(acc[i][j], 0.f);

    int lr0 = tid >> 3, lc0 = tid & 7;
    uint32_t sSt = (uint32_t)((lr0 * KSTR + lc0 * 8) * 2);

    // prefetch stage 0
    {
        uint32_t ab = dynb, bb = dynb + 2 * TILE_BYTES;
#pragma unroll
        for (int it = 0; it < 8; it++) {
            int r = lr0 + it * 16;
            cp16(ab + sSt + it * 16 * KSTR * 2, Ga + (size_t)r * EDIM + lc0 * 8);
            cp16(bb + sSt + it * 16 * KSTR * 2, Gb + (size_t)r * EDIM + lc0 * 8);
        }
        cp_commit();
    }

    for (int s = 0; s < NSTAGE; s++) {
        if (s + 1 < NSTAGE) {
            int nb = (s + 1) & 1;
            uint32_t ab = dynb + nb * TILE_BYTES;
            uint32_t bb = dynb + (2 + nb) * TILE_BYTES;
            const __nv_bfloat16* pA = Ga + (s + 1) * BK + lc0 * 8;
            const __nv_bfloat16* pB = Gb + (s + 1) * BK + lc0 * 8;
#pragma unroll
            for (int it = 0; it < 8; it++) {
                int r = lr0 + it * 16;
                cp16(ab + sSt + it * 16 * KSTR * 2, pA + (size_t)r * EDIM);
                cp16(bb + sSt + it * 16 * KSTR * 2, pB + (size_t)r * EDIM);
            }
            cp_commit();
            cp_wait<1>();
        } else {
            cp_wait<0>();
        }
        __syncthreads();

        const __nv_bfloat16* cA = dyn + (s & 1) * TILE_ELEMS;
        const __nv_bfloat16* cB = dyn + (2 + (s & 1)) * TILE_ELEMS;
#pragma unroll
        for (int kk = 0; kk < BK; kk += 16) {
            wmma::fragment<wmma::matrix_a, 16, 16, 16, __nv_bfloat16, wmma::row_major> fa[4];
            wmma::fragment<wmma::matrix_b, 16, 16, 16, __nv_bfloat16, wmma::col_major> fb[4];
#pragma unroll
            for (int i = 0; i < 4; i++)
                wmma::load_matrix_sync(fa[i], &cA[(wr * 64 + i * 16) * KSTR + kk], KSTR);
#pragma unroll
            for (int j = 0; j < 4; j++)
                wmma::load_matrix_sync(fb[j], &cB[(wc * 64 + j * 16) * KSTR + kk], KSTR);
#pragma unroll
            for (int i = 0; i < 4; i++)
#pragma unroll
                for (int j = 0; j < 4; j++)
                    wmma::mma_sync(acc[i][j], fa[i], fb[j], acc[i][j]);
        }
        __syncthreads();
    }

    if (mode == 0) {
        float* stage = (float*)dyn;
        float* stw = stage + wid * 16 * 68;
        int r = lane >> 1, half = lane & 1;
#pragma unroll
        for (int i = 0; i < 4; i++) {
#pragma unroll
            for (int j = 0; j < 4; j++)
                wmma::store_matrix_sync(&stw[j * 16], acc[i][j], 68, wmma::mem_row_major);
            __syncwarp();
            float x[32];
#pragma unroll
            for (int q = 0; q < 32; q++) x[q] = stw[r * 68 + half * 32 + q] * 20.f;
            float M = x[0];
#pragma unroll
            for (int q = 1; q < 32; q++) M = fmaxf(M, x[q]);
            M = fmaxf(M, __shfl_xor_sync(0xffffffffu, M, 1));
            float s = 0.f;
#pragma unroll
            for (int q = 0; q < 32; q++) s += __expf(x[q] - M);
            s += __shfl_xor_sync(0xffffffffu, s, 1);
            if (half == 0) {
                int grow = m0 + wr * 64 + i * 16 + r;
                int pcol = nt * 2 + wc;
                g_pmax[(size_t)grow * PCOLS + pcol] = M;
                g_psum[(size_t)grow * PCOLS + pcol] = s;
            }
            __syncwarp();
        }
    } else {
#pragma unroll
        for (int i = 0; i < 4; i++)
#pragma unroll
            for (int j = 0; j < 4; j++)
                wmma::store_matrix_sync(
                    &dst[(size_t)(m0 + wr * 64 + i * 16) * BDIM + n0 + wc * 64 + j * 16],
                    acc[i][j], BDIM, wmma::mem_row_major);
        if (bx != by) {
#pragma unroll
            for (int i = 0; i < 4; i++)
#pragma unroll
                for (int j = 0; j < 4; j++)
                    wmma::store_matrix_sync(
                        &dst[(size_t)(n0 + wc * 64 + j * 16) * BDIM + m0 + wr * 64 + i * 16],
                        acc[i][j], BDIM, wmma::mem_col_major);
        }
    }
}

// ======= fused per-row kernel: KD (2-pass KL) + LSE combine + target dot
//         + last-block finalize (no separate finalize launch) =======
// KL identity: kl = w/Zt + (Ms + ln Zs) - (Mt + ln Zt),
//   w = sum_j exp(b_j - Mt) * (b_j - a_j)
__global__ void __launch_bounds__(256) row_kernel(const int* __restrict__ epoch_p,
                                                  float* __restrict__ out, int out_size) {
    __shared__ float ssr[BDIM];       // scaled student row
    __shared__ float str[BDIM];       // scaled teacher row
    int row = blockIdx.x, tid = threadIdx.x;
    int li = g_labels[row];

    const float4* sr4 = (const float4*)(g_sim + (size_t)row * BDIM);
    const float4* tr4 = (const float4*)(g_tsim + (size_t)row * BDIM);
    const int4* lb4 = (const int4*)g_labels;
    float ms = -CUDART_INF_F, mt = -CUDART_INF_F;
#pragma unroll
    for (int it = 0; it < 2; it++) {
        int j4 = it * 256 + tid;          // float4 index 0..511
        int4 lv = lb4[j4];
        float4 a = sr4[j4], b = tr4[j4];
        float s0 = (lv.x == li) ? 0.25f : 0.125f;
        float s1 = (lv.y == li) ? 0.25f : 0.125f;
        float s2 = (lv.z == li) ? 0.25f : 0.125f;
        float s3 = (lv.w == li) ? 0.25f : 0.125f;
        a.x *= s0; a.y *= s1; a.z *= s2; a.w *= s3;
        b.x *= s0; b.y *= s1; b.z *= s2; b.w *= s3;
        *(float4*)&ssr[j4 * 4] = a;
        *(float4*)&str[j4 * 4] = b;
        ms = fmaxf(ms, fmaxf(fmaxf(a.x, a.y), fmaxf(a.z, a.w)));
        mt = fmaxf(mt, fmaxf(fmaxf(b.x, b.y), fmaxf(b.z, b.w)));
    }
    float Ms = blkred(ms, 1);
    float Mt = blkred(mt, 1);

    float zs = 0.f, zt = 0.f, wacc = 0.f;
#pragma unroll
    for (int it = 0; it < 2; it++) {
        int j4 = it * 256 + tid;
        float4 a = *(float4*)&ssr[j4 * 4];
        float4 b = *(float4*)&str[j4 * 4];
        zs += __expf(a.x - Ms) + __expf(a.y - Ms) + __expf(a.z - Ms) + __expf(a.w - Ms);
        float e0 = __expf(b.x - Mt), e1 = __expf(b.y - Mt);
        float e2 = __expf(b.z - Mt), e3 = __expf(b.w - Mt);
        zt += e0 + e1 + e2 + e3;
        wacc += e0 * (b.x - a.x) + e1 * (b.y - a.y) + e2 * (b.z - a.z) + e3 * (b.w - a.w);
    }
    float Zs = blkred(zs, 0);
    float Zt = blkred(zt, 0);
    float W  = blkred(wacc, 0);

    const __nv_bfloat16* xv = g_xb + (size_t)row * EDIM;
    const __nv_bfloat16* wv = g_w + (size_t)li * EDIM;
    float d = 0.f;
    for (int i = tid; i < EDIM; i += 256)
        d += __bfloat162float(xv[i]) * __bfloat162float(wv[i]);
    float tgt20 = blkred(d, 0) * 20.f;

    float pm = g_pmax[(size_t)row * PCOLS + tid];
    float pp = g_psum[(size_t)row * PCOLS + tid];
    float M = blkred(pm, 1);
    float S = blkred(pp * __expf(pm - M), 0);

    __shared__ int s_last;
    if (tid == 0) {
        g_kd_row[row] = W / Zt + (Ms + logf(Zs)) - (Mt + logf(Zt));
        g_rank_row[row] = logf(S) + M - tgt20;
        __threadfence();
        unsigned int prev = atomicAdd(&g_done, 1u);
        s_last = (prev == (unsigned int)(BDIM - 1)) ? 1 : 0;
    }
    __syncthreads();

    if (s_last) {
        __threadfence();
        float r = 0.f, k = 0.f;
        for (int i = tid; i < BDIM; i += 256) { r += g_rank_row[i]; k += g_kd_row[i]; }
        r = blkred(r, 0);
        k = blkred(k, 0);
        if (tid == 0) {
            float lr = r / (float)BDIM;
            float lk = k / (float)BDIM;
            int ei = *epoch_p;
            float ef = (ei >= 0 && ei < 10000000) ? (float)ei
                                                  : *reinterpret_cast<const float*>(epoch_p);
            float ramp = (ef / 150.f) * 16.0f;
            out[0] = lr + ramp * lk;
            if (out_size > 1) out[1] = lr;
            if (out_size > 2) out[2] = lk;
        }
    }
}

// ---------------- launch ----------------
extern "C" void kernel_launch(void* const* d_in, const int* in_sizes, int n_in,
                              void* d_out, int out_size) {
    const float* batch = (const float*)d_in[0];
    const float* teach = (const float*)d_in[1];
    const float* cmap  = (const float*)d_in[2];
    const void*  labels = d_in[3];
    const int*   epoch = (const int*)d_in[4];
    float* out = (float*)d_out;

    cudaFuncSetAttribute(fused_gemm_kernel,
                         cudaFuncAttributeMaxDynamicSharedMemorySize, DYNB);

    prep_kernel<<<NPREP_TOTAL, 128>>>(cmap, batch, teach, labels);
    fused_gemm_kernel<<<NLOGIT + 2 * NPAIR, 128, DYNB>>>();
    row_kernel<<<BDIM, 256>>>(epoch, out, out_size);
}

// round 15
// speedup vs baseline: 1.0602x; 1.0125x over previous
#include <cuda_runtime.h>
#include <cuda_bf16.h>
#include <mma.h>
#include <math_constants.h>
#include <cstdint>
using namespace nvcuda;

#define BDIM 2048
#define EDIM 512
#define CDIM 16384
#define PCOLS 256              // per-row LSE partials: CDIM/64

// ---------------- scratch (static device arrays; no allocation) ----------------
__device__ __nv_bfloat16 g_w[(size_t)CDIM * EDIM];     // 16 MiB
__device__ __nv_bfloat16 g_xb[(size_t)BDIM * EDIM];    // 2 MiB
__device__ __nv_bfloat16 g_tb[(size_t)BDIM * EDIM];    // 2 MiB
__device__ float g_sim[(size_t)BDIM * BDIM];           // 16 MiB
__device__ float g_tsim[(size_t)BDIM * BDIM];          // 16 MiB
__device__ float g_pmax[(size_t)BDIM * PCOLS];         // 2 MiB
__device__ float g_psum[(size_t)BDIM * PCOLS];         // 2 MiB
__device__ float g_rank_row[BDIM];
__device__ float g_kd_row[BDIM];
__device__ int   g_labels[BDIM];
__device__ unsigned int g_done;          // reset each call in prep_kernel

// ---------------- block-wide reduction (op=0 sum, op=1 max) ----------------
__device__ __forceinline__ float blkred(float v, int op) {
    __shared__ float tmp[32];
    int lane = threadIdx.x & 31, w = threadIdx.x >> 5;
#pragma unroll
    for (int o = 16; o > 0; o >>= 1) {
        float u = __shfl_xor_sync(0xffffffffu, v, o);
        v = op ? fmaxf(v, u) : v + u;
    }
    __syncthreads();
    if (lane == 0) tmp[w] = v;
    __syncthreads();
    int nw = blockDim.x >> 5;
    if (w == 0) {
        v = (lane < nw) ? tmp[lane] : (op ? -CUDART_INF_F : 0.f);
#pragma unroll
        for (int o = 16; o > 0; o >>= 1) {
            float u = __shfl_xor_sync(0xffffffffu, v, o);
            v = op ? fmaxf(v, u) : v + u;
        }
        if (lane == 0) tmp[0] = v;
    }
    __syncthreads();
    return tmp[0];
}

// ---------------- fused prep: normalize_w | cast | labels (one launch) ----------------
#define NORM_BLOCKS (CDIM / 4)                // 4096
#define CAST_BLOCKS 1024                      // 128 thr x 2 float4 per tensor
#define NPREP_TOTAL (NORM_BLOCKS + CAST_BLOCKS + 1)

__global__ void __launch_bounds__(128) prep_kernel(const float* __restrict__ cm,
                                                   const float* __restrict__ x,
                                                   const float* __restrict__ t,
                                                   const void* __restrict__ lp) {
    int bid = blockIdx.x, tid = threadIdx.x;
    int lane = tid & 31, warp = tid >> 5;
    if (bid < NORM_BLOCKS) {
        int row = bid * 4 + warp;
        const float4* src = reinterpret_cast<const float4*>(cm) + (size_t)row * (EDIM / 4);
        float4 v[4];
#pragma unroll
        for (int q = 0; q < 4; q++) v[q] = src[lane + 32 * q];
        float ss = 0.f;
#pragma unroll
        for (int q = 0; q < 4; q++)
            ss += v[q].x * v[q].x + v[q].y * v[q].y + v[q].z * v[q].z + v[q].w * v[q].w;
#pragma unroll
        for (int o = 16; o > 0; o >>= 1) ss += __shfl_xor_sync(0xffffffffu, ss, o);
        float r = rsqrtf(ss);
        uint2* dstrow = reinterpret_cast<uint2*>(g_w + (size_t)row * EDIM);
#pragma unroll
        for (int q = 0; q < 4; q++) {
            __nv_bfloat162 lo = __floats2bfloat162_rn(v[q].x * r, v[q].y * r);
            __nv_bfloat162 hi = __floats2bfloat162_rn(v[q].z * r, v[q].w * r);
            uint2 u;
            u.x = *reinterpret_cast<uint32_t*>(&lo);
            u.y = *reinterpret_cast<uint32_t*>(&hi);
            dstrow[lane + 32 * q] = u;
        }
    } else if (bid < NORM_BLOCKS + CAST_BLOCKS) {
        int base = (bid - NORM_BLOCKS) * 256 + tid;   // float4 index, stride grid
        const float4* x4 = reinterpret_cast<const float4*>(x);
        const float4* t4 = reinterpret_cast<const float4*>(t);
        uint2* xb2 = reinterpret_cast<uint2*>(g_xb);
        uint2* tb2 = reinterpret_cast<uint2*>(g_tb);
#pragma unroll
        for (int p = 0; p < 2; p++) {
            int i = base + p * 128;                    // 262144 float4 total
            float4 a = x4[i], b = t4[i];
            __nv_bfloat162 a0 = __floats2bfloat162_rn(a.x, a.y);
            __nv_bfloat162 a1 = __floats2bfloat162_rn(a.z, a.w);
            __nv_bfloat162 b0 = __floats2bfloat162_rn(b.x, b.y);
            __nv_bfloat162 b1 = __floats2bfloat162_rn(b.z, b.w);
            uint2 ua, ub;
            ua.x = *reinterpret_cast<uint32_t*>(&a0);
            ua.y = *reinterpret_cast<uint32_t*>(&a1);
            ub.x = *reinterpret_cast<uint32_t*>(&b0);
            ub.y = *reinterpret_cast<uint32_t*>(&b1);
            xb2[i] = ua;
            tb2[i] = ub;
        }
    } else {
        __shared__ int is32;
        const long long* l64 = (const long long*)lp;
        const int* l32 = (const int*)lp;
        if (tid == 0) { is32 = 0; g_done = 0u; }   // reset finalize counter
        __syncthreads();
        for (int i = tid; i < 1024; i += 128) {
            long long v = l64[i];
            if (v < 0 || v >= 256) is32 = 1;
        }
        __syncthreads();
        int f = is32;
        for (int i = tid; i < BDIM; i += 128)
            g_labels[i] = f ? l32[i] : (int)l64[i];
    }
}

// =============== fused bf16 GEMM: C[m,n] = sum_k A[m,k]*B[n,k] ===============
// One launch: blocks [0,2048) = logits tiles w/ fused LSE partials;
//             blocks [2048,2320) = symmetric Gram upper-tri tiles (+mirror store).
#define BM 128
#define BN 128
#define BK 64
#define KSTR (BK + 8)          // 72 bf16 = 144B row stride (16B multiple)
#define NSTAGE (EDIM / BK)     // 8
#define TILE_ELEMS (BM * KSTR) // 9216 bf16 per tile buffer
#define TILE_BYTES (TILE_ELEMS * 2)
#define DYNB (4 * TILE_BYTES)  // A0,A1,B0,B1 = 73728 B
#define NPAIR 136              // 16*17/2 upper-tri 128x128 tiles of 2048x2048
#define NLOGIT 2048

__device__ __forceinline__ void cp16(uint32_t s, const void* g) {
    asm volatile("cp.async.cg.shared.global [%0], [%1], 16;\n" :: "r"(s), "l"(g));
}
__device__ __forceinline__ void cp_commit() {
    asm volatile("cp.async.commit_group;\n");
}
template <int N>
__device__ __forceinline__ void cp_wait() {
    asm volatile("cp.async.wait_group %0;\n" :: "n"(N));
}

__global__ void __launch_bounds__(128, 3) fused_gemm_kernel() {
    extern __shared__ __nv_bfloat16 dyn[];  // [A0 A1 B0 B1]

    int bid = blockIdx.x;
    int tid = threadIdx.x;
    int wid = tid >> 5, lane = tid & 31;
    int wr = wid >> 1, wc = wid & 1;        // 2x2 warps, each 64x64

    const __nv_bfloat16 *A, *B;
    float* dst = nullptr;
    int m0, n0, mode, nt = 0, bx = 0, by = 0;
    if (bid < NLOGIT) {
        mode = 0;
        nt = bid & 127;
        m0 = (bid >> 7) * BM;
        n0 = nt * BN;
        A = g_xb; B = g_w;
    } else {
        mode = 1;
        int g = bid - NLOGIT;
        int which = (g >= NPAIR) ? 1 : 0;
        int pair = g - which * NPAIR;
        bx = (int)((sqrtf(8.f * pair + 1.f) - 1.f) * 0.5f);
        if (bx * (bx + 1) / 2 > pair) bx--;
        if ((bx + 1) * (bx + 2) / 2 <= pair) bx++;
        by = pair - bx * (bx + 1) / 2;       // by <= bx
        m0 = by * BM;
        n0 = bx * BN;
        A = which ? g_tb : g_xb;
        B = A;
        dst = which ? g_tsim : g_sim;
    }

    uint32_t dynb = (uint32_t)__cvta_generic_to_shared(dyn);
    const __nv_bfloat16* Ga = A + (size_t)m0 * EDIM;
    const __nv_bfloat16* Gb = B + (size_t)n0 * EDIM;

    wmma::fragment<wmma::accumulator, 16, 16, 16, float> acc[4][4];
#pragma unroll
    for (int i = 0; i < 4; i++)
#pragma unroll
        for (int j = 0; j < 4; j++) wmma::fill_fragment(acc[i][j], 0.f);

    int lr0 = tid >> 3, lc0 = tid & 7;
    uint32_t sSt = (uint32_t)((lr0 * KSTR + lc0 * 8) * 2);

    // prefetch stage 0
    {
        uint32_t ab = dynb, bb = dynb + 2 * TILE_BYTES;
#pragma unroll
        for (int it = 0; it < 8; it++) {
            int r = lr0 + it * 16;
            cp16(ab + sSt + it * 16 * KSTR * 2, Ga + (size_t)r * EDIM + lc0 * 8);
            cp16(bb + sSt + it * 16 * KSTR * 2, Gb + (size_t)r * EDIM + lc0 * 8);
        }
        cp_commit();
    }

    for (int s = 0; s < NSTAGE; s++) {
        if (s + 1 < NSTAGE) {
            int nb = (s + 1) & 1;
            uint32_t ab = dynb + nb * TILE_BYTES;
            uint32_t bb = dynb + (2 + nb) * TILE_BYTES;
            const __nv_bfloat16* pA = Ga + (s + 1) * BK + lc0 * 8;
            const __nv_bfloat16* pB = Gb + (s + 1) * BK + lc0 * 8;
#pragma unroll
            for (int it = 0; it < 8; it++) {
                int r = lr0 + it * 16;
                cp16(ab + sSt + it * 16 * KSTR * 2, pA + (size_t)r * EDIM);
                cp16(bb + sSt + it * 16 * KSTR * 2, pB + (size_t)r * EDIM);
            }
            cp_commit();
            cp_wait<1>();
        } else {
            cp_wait<0>();
        }
        __syncthreads();

        const __nv_bfloat16* cA = dyn + (s & 1) * TILE_ELEMS;
        const __nv_bfloat16* cB = dyn + (2 + (s & 1)) * TILE_ELEMS;
#pragma unroll
        for (int kk = 0; kk < BK; kk += 16) {
            wmma::fragment<wmma::matrix_a, 16, 16, 16, __nv_bfloat16, wmma::row_major> fa[4];
            wmma::fragment<wmma::matrix_b, 16, 16, 16, __nv_bfloat16, wmma::col_major> fb[4];
#pragma unroll
            for (int i = 0; i < 4; i++)
                wmma::load_matrix_sync(fa[i], &cA[(wr * 64 + i * 16) * KSTR + kk], KSTR);
#pragma unroll
            for (int j = 0; j < 4; j++)
                wmma::load_matrix_sync(fb[j], &cB[(wc * 64 + j * 16) * KSTR + kk], KSTR);
#pragma unroll
            for (int i = 0; i < 4; i++)
#pragma unroll
                for (int j = 0; j < 4; j++)
                    wmma::mma_sync(acc[i][j], fa[i], fb[j], acc[i][j]);
        }
        __syncthreads();
    }

    if (mode == 0) {
        float* stage = (float*)dyn;
        float* stw = stage + wid * 16 * 68;
        int r = lane >> 1, half = lane & 1;
#pragma unroll
        for (int i = 0; i < 4; i++) {
#pragma unroll
            for (int j = 0; j < 4; j++)
                wmma::store_matrix_sync(&stw[j * 16], acc[i][j], 68, wmma::mem_row_major);
            __syncwarp();
            float x[32];
#pragma unroll
            for (int q = 0; q < 32; q++) x[q] = stw[r * 68 + half * 32 + q] * 20.f;
            float M = x[0];
#pragma unroll
            for (int q = 1; q < 32; q++) M = fmaxf(M, x[q]);
            M = fmaxf(M, __shfl_xor_sync(0xffffffffu, M, 1));
            float s = 0.f;
#pragma unroll
            for (int q = 0; q < 32; q++) s += __expf(x[q] - M);
            s += __shfl_xor_sync(0xffffffffu, s, 1);
            if (half == 0) {
                int grow = m0 + wr * 64 + i * 16 + r;
                int pcol = nt * 2 + wc;
                g_pmax[(size_t)grow * PCOLS + pcol] = M;
                g_psum[(size_t)grow * PCOLS + pcol] = s;
            }
            __syncwarp();
        }
    } else {
#pragma unroll
        for (int i = 0; i < 4; i++)
#pragma unroll
            for (int j = 0; j < 4; j++)
                wmma::store_matrix_sync(
                    &dst[(size_t)(m0 + wr * 64 + i * 16) * BDIM + n0 + wc * 64 + j * 16],
                    acc[i][j], BDIM, wmma::mem_row_major);
        if (bx != by) {
#pragma unroll
            for (int i = 0; i < 4; i++)
#pragma unroll
                for (int j = 0; j < 4; j++)
                    wmma::store_matrix_sync(
                        &dst[(size_t)(n0 + wc * 64 + j * 16) * BDIM + m0 + wr * 64 + i * 16],
                        acc[i][j], BDIM, wmma::mem_col_major);
        }
    }
}

// ======= fused per-row kernel: KD (2-pass KL, register-resident rows)
//         + LSE combine + target dot + last-block finalize =======
// KL identity: kl = w/Zt + (Ms + ln Zs) - (Mt + ln Zt),
//   w = sum_j exp(b_j - Mt) * (b_j - a_j)
__global__ void __launch_bounds__(256) row_kernel(const int* __restrict__ epoch_p,
                                                  float* __restrict__ out, int out_size) {
    int row = blockIdx.x, tid = threadIdx.x;
    int li = g_labels[row];

    // --- pass 1: load sim/tsim as float4 into REGISTERS, scale, track maxes ---
    const float4* sr4 = (const float4*)(g_sim + (size_t)row * BDIM);
    const float4* tr4 = (const float4*)(g_tsim + (size_t)row * BDIM);
    const int4* lb4 = (const int4*)g_labels;
    float4 a[2], b[2];
    float ms = -CUDART_INF_F, mt = -CUDART_INF_F;
#pragma unroll
    for (int it = 0; it < 2; it++) {
        int j4 = it * 256 + tid;          // float4 index 0..511
        int4 lv = lb4[j4];
        a[it] = sr4[j4];
        b[it] = tr4[j4];
        float s0 = (lv.x == li) ? 0.25f : 0.125f;
        float s1 = (lv.y == li) ? 0.25f : 0.125f;
        float s2 = (lv.z == li) ? 0.25f : 0.125f;
        float s3 = (lv.w == li) ? 0.25f : 0.125f;
        a[it].x *= s0; a[it].y *= s1; a[it].z *= s2; a[it].w *= s3;
        b[it].x *= s0; b[it].y *= s1; b[it].z *= s2; b[it].w *= s3;
        ms = fmaxf(ms, fmaxf(fmaxf(a[it].x, a[it].y), fmaxf(a[it].z, a[it].w)));
        mt = fmaxf(mt, fmaxf(fmaxf(b[it].x, b[it].y), fmaxf(b[it].z, b[it].w)));
    }
    float Ms = blkred(ms, 1);
    float Mt = blkred(mt, 1);

    // --- pass 2 (registers): zs, zt, w in one sweep ---
    float zs = 0.f, zt = 0.f, wacc = 0.f;
#pragma unroll
    for (int it = 0; it < 2; it++) {
        zs += __expf(a[it].x - Ms) + __expf(a[it].y - Ms)
            + __expf(a[it].z - Ms) + __expf(a[it].w - Ms);
        float e0 = __expf(b[it].x - Mt), e1 = __expf(b[it].y - Mt);
        float e2 = __expf(b[it].z - Mt), e3 = __expf(b[it].w - Mt);
        zt += e0 + e1 + e2 + e3;
        wacc += e0 * (b[it].x - a[it].x) + e1 * (b[it].y - a[it].y)
              + e2 * (b[it].z - a[it].z) + e3 * (b[it].w - a[it].w);
    }
    float Zs = blkred(zs, 0);
    float Zt = blkred(zt, 0);
    float W  = blkred(wacc, 0);

    // --- LSE combine + target dot ---
    const __nv_bfloat16* xv = g_xb + (size_t)row * EDIM;
    const __nv_bfloat16* wv = g_w + (size_t)li * EDIM;
    float d = 0.f;
    for (int i = tid; i < EDIM; i += 256)
        d += __bfloat162float(xv[i]) * __bfloat162float(wv[i]);
    float tgt20 = blkred(d, 0) * 20.f;

    float pm = g_pmax[(size_t)row * PCOLS + tid];
    float pp = g_psum[(size_t)row * PCOLS + tid];
    float M = blkred(pm, 1);
    float S = blkred(pp * __expf(pm - M), 0);

    __shared__ int s_last;
    if (tid == 0) {
        g_kd_row[row] = W / Zt + (Ms + logf(Zs)) - (Mt + logf(Zt));
        g_rank_row[row] = logf(S) + M - tgt20;
        __threadfence();
        unsigned int prev = atomicAdd(&g_done, 1u);
        s_last = (prev == (unsigned int)(BDIM - 1)) ? 1 : 0;
    }
    __syncthreads();

    if (s_last) {
        __threadfence();
        float r = 0.f, k = 0.f;
        for (int i = tid; i < BDIM; i += 256) { r += g_rank_row[i]; k += g_kd_row[i]; }
        r = blkred(r, 0);
        k = blkred(k, 0);
        if (tid == 0) {
            float lr = r / (float)BDIM;
            float lk = k / (float)BDIM;
            int ei = *epoch_p;
            float ef = (ei >= 0 && ei < 10000000) ? (float)ei
                                                  : *reinterpret_cast<const float*>(epoch_p);
            float ramp = (ef / 150.f) * 16.0f;
            out[0] = lr + ramp * lk;
            if (out_size > 1) out[1] = lr;
            if (out_size > 2) out[2] = lk;
        }
    }
}

// ---------------- launch ----------------
extern "C" void kernel_launch(void* const* d_in, const int* in_sizes, int n_in,
                              void* d_out, int out_size) {
    const float* batch = (const float*)d_in[0];
    const float* teach = (const float*)d_in[1];
    const float* cmap  = (const float*)d_in[2];
    const void*  labels = d_in[3];
    const int*   epoch = (const int*)d_in[4];
    float* out = (float*)d_out;

    cudaFuncSetAttribute(fused_gemm_kernel,
                         cudaFuncAttributeMaxDynamicSharedMemorySize, DYNB);

    prep_kernel<<<NPREP_TOTAL, 128>>>(cmap, batch, teach, labels);
    fused_gemm_kernel<<<NLOGIT + 2 * NPAIR, 128, DYNB>>>();
    row_kernel<<<BDIM, 256>>>(epoch, out, out_size);
}

// round 16
// speedup vs baseline: 1.0669x; 1.0063x over previous
#include <cuda_runtime.h>
#include <cuda_bf16.h>
#include <mma.h>
#include <math_constants.h>
#include <cstdint>
using namespace nvcuda;

#define BDIM 2048
#define EDIM 512
#define CDIM 16384
#define PCOLS 256              // per-row LSE partials: CDIM/64

// ---------------- scratch (static device arrays; no allocation) ----------------
__device__ __nv_bfloat16 g_w[(size_t)CDIM * EDIM];     // 16 MiB
__device__ __nv_bfloat16 g_xb[(size_t)BDIM * EDIM];    // 2 MiB
__device__ __nv_bfloat16 g_tb[(size_t)BDIM * EDIM];    // 2 MiB
__device__ float g_sim[(size_t)BDIM * BDIM];           // 16 MiB
__device__ float g_tsim[(size_t)BDIM * BDIM];          // 16 MiB
__device__ float g_pmax[(size_t)BDIM * PCOLS];         // 2 MiB
__device__ float g_psum[(size_t)BDIM * PCOLS];         // 2 MiB
__device__ float g_rank_row[BDIM];
__device__ float g_kd_row[BDIM];
__device__ int   g_labels[BDIM];
__device__ unsigned int g_done;          // reset each call in prep_kernel

// ---------------- block-wide reduction (op=0 sum, op=1 max) ----------------
__device__ __forceinline__ float blkred(float v, int op) {
    __shared__ float tmp[32];
    int lane = threadIdx.x & 31, w = threadIdx.x >> 5;
#pragma unroll
    for (int o = 16; o > 0; o >>= 1) {
        float u = __shfl_xor_sync(0xffffffffu, v, o);
        v = op ? fmaxf(v, u) : v + u;
    }
    __syncthreads();
    if (lane == 0) tmp[w] = v;
    __syncthreads();
    int nw = blockDim.x >> 5;
    if (w == 0) {
        v = (lane < nw) ? tmp[lane] : (op ? -CUDART_INF_F : 0.f);
#pragma unroll
        for (int o = 16; o > 0; o >>= 1) {
            float u = __shfl_xor_sync(0xffffffffu, v, o);
            v = op ? fmaxf(v, u) : v + u;
        }
        if (lane == 0) tmp[0] = v;
    }
    __syncthreads();
    return tmp[0];
}

// ---- batched block reductions: 2-wide max and 4-wide sum (one barrier pair each) ----
__device__ __forceinline__ void blkred_max2(float& va, float& vb) {
    __shared__ float t2[64];
    int lane = threadIdx.x & 31, w = threadIdx.x >> 5;
#pragma unroll
    for (int o = 16; o > 0; o >>= 1) {
        va = fmaxf(va, __shfl_xor_sync(0xffffffffu, va, o));
        vb = fmaxf(vb, __shfl_xor_sync(0xffffffffu, vb, o));
    }
    __syncthreads();
    if (lane == 0) { t2[w] = va; t2[32 + w] = vb; }
    __syncthreads();
    int nw = blockDim.x >> 5;
    if (w == 0) {
        float a = (lane < nw) ? t2[lane] : -CUDART_INF_F;
        float b = (lane < nw) ? t2[32 + lane] : -CUDART_INF_F;
#pragma unroll
        for (int o = 16; o > 0; o >>= 1) {
            a = fmaxf(a, __shfl_xor_sync(0xffffffffu, a, o));
            b = fmaxf(b, __shfl_xor_sync(0xffffffffu, b, o));
        }
        if (lane == 0) { t2[0] = a; t2[32] = b; }
    }
    __syncthreads();
    va = t2[0]; vb = t2[32];
}

__device__ __forceinline__ void blkred_sum4(float& v0, float& v1, float& v2, float& v3) {
    __shared__ float t4[128];
    int lane = threadIdx.x & 31, w = threadIdx.x >> 5;
#pragma unroll
    for (int o = 16; o > 0; o >>= 1) {
        v0 += __shfl_xor_sync(0xffffffffu, v0, o);
        v1 += __shfl_xor_sync(0xffffffffu, v1, o);
        v2 += __shfl_xor_sync(0xffffffffu, v2, o);
        v3 += __shfl_xor_sync(0xffffffffu, v3, o);
    }
    __syncthreads();
    if (lane == 0) { t4[w] = v0; t4[32 + w] = v1; t4[64 + w] = v2; t4[96 + w] = v3; }
    __syncthreads();
    int nw = blockDim.x >> 5;
    if (w == 0) {
        float a = (lane < nw) ? t4[lane] : 0.f;
        float b = (lane < nw) ? t4[32 + lane] : 0.f;
        float c = (lane < nw) ? t4[64 + lane] : 0.f;
        float d = (lane < nw) ? t4[96 + lane] : 0.f;
#pragma unroll
        for (int o = 16; o > 0; o >>= 1) {
            a += __shfl_xor_sync(0xffffffffu, a, o);
            b += __shfl_xor_sync(0xffffffffu, b, o);
            c += __shfl_xor_sync(0xffffffffu, c, o);
            d += __shfl_xor_sync(0xffffffffu, d, o);
        }
        if (lane == 0) { t4[0] = a; t4[32] = b; t4[64] = c; t4[96] = d; }
    }
    __syncthreads();
    v0 = t4[0]; v1 = t4[32]; v2 = t4[64]; v3 = t4[96];
}

// ---------------- fused prep: normalize_w | cast | labels (one launch) ----------------
#define NORM_BLOCKS (CDIM / 4)                // 4096
#define CAST_BLOCKS 1024                      // 128 thr x 2 float4 per tensor
#define NPREP_TOTAL (NORM_BLOCKS + CAST_BLOCKS + 1)

__global__ void __launch_bounds__(128) prep_kernel(const float* __restrict__ cm,
                                                   const float* __restrict__ x,
                                                   const float* __restrict__ t,
                                                   const void* __restrict__ lp) {
    int bid = blockIdx.x, tid = threadIdx.x;
    int lane = tid & 31, warp = tid >> 5;
    if (bid < NORM_BLOCKS) {
        int row = bid * 4 + warp;
        const float4* src = reinterpret_cast<const float4*>(cm) + (size_t)row * (EDIM / 4);
        float4 v[4];
#pragma unroll
        for (int q = 0; q < 4; q++) v[q] = src[lane + 32 * q];
        float ss = 0.f;
#pragma unroll
        for (int q = 0; q < 4; q++)
            ss += v[q].x * v[q].x + v[q].y * v[q].y + v[q].z * v[q].z + v[q].w * v[q].w;
#pragma unroll
        for (int o = 16; o > 0; o >>= 1) ss += __shfl_xor_sync(0xffffffffu, ss, o);
        float r = rsqrtf(ss);
        uint2* dstrow = reinterpret_cast<uint2*>(g_w + (size_t)row * EDIM);
#pragma unroll
        for (int q = 0; q < 4; q++) {
            __nv_bfloat162 lo = __floats2bfloat162_rn(v[q].x * r, v[q].y * r);
            __nv_bfloat162 hi = __floats2bfloat162_rn(v[q].z * r, v[q].w * r);
            uint2 u;
            u.x = *reinterpret_cast<uint32_t*>(&lo);
            u.y = *reinterpret_cast<uint32_t*>(&hi);
            dstrow[lane + 32 * q] = u;
        }
    } else if (bid < NORM_BLOCKS + CAST_BLOCKS) {
        int base = (bid - NORM_BLOCKS) * 256 + tid;   // float4 index, stride grid
        const float4* x4 = reinterpret_cast<const float4*>(x);
        const float4* t4 = reinterpret_cast<const float4*>(t);
        uint2* xb2 = reinterpret_cast<uint2*>(g_xb);
        uint2* tb2 = reinterpret_cast<uint2*>(g_tb);
#pragma unroll
        for (int p = 0; p < 2; p++) {
            int i = base + p * 128;                    // 262144 float4 total
            float4 a = x4[i], b = t4[i];
            __nv_bfloat162 a0 = __floats2bfloat162_rn(a.x, a.y);
            __nv_bfloat162 a1 = __floats2bfloat162_rn(a.z, a.w);
            __nv_bfloat162 b0 = __floats2bfloat162_rn(b.x, b.y);
            __nv_bfloat162 b1 = __floats2bfloat162_rn(b.z, b.w);
            uint2 ua, ub;
            ua.x = *reinterpret_cast<uint32_t*>(&a0);
            ua.y = *reinterpret_cast<uint32_t*>(&a1);
            ub.x = *reinterpret_cast<uint32_t*>(&b0);
            ub.y = *reinterpret_cast<uint32_t*>(&b1);
            xb2[i] = ua;
            tb2[i] = ub;
        }
    } else {
        __shared__ int is32;
        const long long* l64 = (const long long*)lp;
        const int* l32 = (const int*)lp;
        if (tid == 0) { is32 = 0; g_done = 0u; }   // reset finalize counter
        __syncthreads();
        for (int i = tid; i < 1024; i += 128) {
            long long v = l64[i];
            if (v < 0 || v >= 256) is32 = 1;
        }
        __syncthreads();
        int f = is32;
        for (int i = tid; i < BDIM; i += 128)
            g_labels[i] = f ? l32[i] : (int)l64[i];
    }
}

// =============== fused bf16 GEMM: C[m,n] = sum_k A[m,k]*B[n,k] ===============
// One launch: blocks [0,2048) = logits tiles w/ fused LSE partials;
//             blocks [2048,2320) = symmetric Gram upper-tri tiles (+mirror store).
#define BM 128
#define BN 128
#define BK 64
#define KSTR (BK + 8)          // 72 bf16 = 144B row stride (16B multiple)
#define NSTAGE (EDIM / BK)     // 8
#define TILE_ELEMS (BM * KSTR) // 9216 bf16 per tile buffer
#define TILE_BYTES (TILE_ELEMS * 2)
#define DYNB (4 * TILE_BYTES)  // A0,A1,B0,B1 = 73728 B
#define NPAIR 136              // 16*17/2 upper-tri 128x128 tiles of 2048x2048
#define NLOGIT 2048

__device__ __forceinline__ void cp16(uint32_t s, const void* g) {
    asm volatile("cp.async.cg.shared.global [%0], [%1], 16;\n" :: "r"(s), "l"(g));
}
__device__ __forceinline__ void cp_commit() {
    asm volatile("cp.async.commit_group;\n");
}
template <int N>
__device__ __forceinline__ void cp_wait() {
    asm volatile("cp.async.wait_group %0;\n" :: "n"(N));
}

__global__ void __launch_bounds__(128, 3) fused_gemm_kernel() {
    extern __shared__ __nv_bfloat16 dyn[];  // [A0 A1 B0 B1]

    int bid = blockIdx.x;
    int tid = threadIdx.x;
    int wid = tid >> 5, lane = tid & 31;
    int wr = wid >> 1, wc = wid & 1;        // 2x2 warps, each 64x64

    const __nv_bfloat16 *A, *B;
    float* dst = nullptr;
    int m0, n0, mode, nt = 0, bx = 0, by = 0;
    if (bid < NLOGIT) {
        mode = 0;
        nt = bid & 127;
        m0 = (bid >> 7) * BM;
        n0 = nt * BN;
        A = g_xb; B = g_w;
    } else {
        mode = 1;
        int g = bid - NLOGIT;
        int which = (g >= NPAIR) ? 1 : 0;
        int pair = g - which * NPAIR;
        bx = (int)((sqrtf(8.f * pair + 1.f) - 1.f) * 0.5f);
        if (bx * (bx + 1) / 2 > pair) bx--;
        if ((bx + 1) * (bx + 2) / 2 <= pair) bx++;
        by = pair - bx * (bx + 1) / 2;       // by <= bx
        m0 = by * BM;
        n0 = bx * BN;
        A = which ? g_tb : g_xb;
        B = A;
        dst = which ? g_tsim : g_sim;
    }

    uint32_t dynb = (uint32_t)__cvta_generic_to_shared(dyn);
    const __nv_bfloat16* Ga = A + (size_t)m0 * EDIM;
    const __nv_bfloat16* Gb = B + (size_t)n0 * EDIM;

    wmma::fragment<wmma::accumulator, 16, 16, 16, float> acc[4][4];
#pragma unroll
    for (int i = 0; i < 4; i++)
#pragma unroll
        for (int j = 0; j < 4; j++) wmma::fill_fragment(acc[i][j], 0.f);

    int lr0 = tid >> 3, lc0 = tid & 7;
    uint32_t sSt = (uint32_t)((lr0 * KSTR + lc0 * 8) * 2);

    // prefetch stage 0
    {
        uint32_t ab = dynb, bb = dynb + 2 * TILE_BYTES;
#pragma unroll
        for (int it = 0; it < 8; it++) {
            int r = lr0 + it * 16;
            cp16(ab + sSt + it * 16 * KSTR * 2, Ga + (size_t)r * EDIM + lc0 * 8);
            cp16(bb + sSt + it * 16 * KSTR * 2, Gb + (size_t)r * EDIM + lc0 * 8);
        }
        cp_commit();
    }

    for (int s = 0; s < NSTAGE; s++) {
        if (s + 1 < NSTAGE) {
            int nb = (s + 1) & 1;
            uint32_t ab = dynb + nb * TILE_BYTES;
            uint32_t bb = dynb + (2 + nb) * TILE_BYTES;
            const __nv_bfloat16* pA = Ga + (s + 1) * BK + lc0 * 8;
            const __nv_bfloat16* pB = Gb + (s + 1) * BK + lc0 * 8;
#pragma unroll
            for (int it = 0; it < 8; it++) {
                int r = lr0 + it * 16;
                cp16(ab + sSt + it * 16 * KSTR * 2, pA + (size_t)r * EDIM);
                cp16(bb + sSt + it * 16 * KSTR * 2, pB + (size_t)r * EDIM);
            }
            cp_commit();
            cp_wait<1>();
        } else {
            cp_wait<0>();
        }
        __syncthreads();

        const __nv_bfloat16* cA = dyn + (s & 1) * TILE_ELEMS;
        const __nv_bfloat16* cB = dyn + (2 + (s & 1)) * TILE_ELEMS;
#pragma unroll
        for (int kk = 0; kk < BK; kk += 16) {
            wmma::fragment<wmma::matrix_a, 16, 16, 16, __nv_bfloat16, wmma::row_major> fa[4];
            wmma::fragment<wmma::matrix_b, 16, 16, 16, __nv_bfloat16, wmma::col_major> fb[4];
#pragma unroll
            for (int i = 0; i < 4; i++)
                wmma::load_matrix_sync(fa[i], &cA[(wr * 64 + i * 16) * KSTR + kk], KSTR);
#pragma unroll
            for (int j = 0; j < 4; j++)
                wmma::load_matrix_sync(fb[j], &cB[(wc * 64 + j * 16) * KSTR + kk], KSTR);
#pragma unroll
            for (int i = 0; i < 4; i++)
#pragma unroll
                for (int j = 0; j < 4; j++)
                    wmma::mma_sync(acc[i][j], fa[i], fb[j], acc[i][j]);
        }
        __syncthreads();
    }

    if (mode == 0) {
        float* stage = (float*)dyn;
        float* stw = stage + wid * 16 * 68;
        int r = lane >> 1, half = lane & 1;
#pragma unroll
        for (int i = 0; i < 4; i++) {
#pragma unroll
            for (int j = 0; j < 4; j++)
                wmma::store_matrix_sync(&stw[j * 16], acc[i][j], 68, wmma::mem_row_major);
            __syncwarp();
            float x[32];
#pragma unroll
            for (int q = 0; q < 32; q++) x[q] = stw[r * 68 + half * 32 + q] * 20.f;
            float M = x[0];
#pragma unroll
            for (int q = 1; q < 32; q++) M = fmaxf(M, x[q]);
            M = fmaxf(M, __shfl_xor_sync(0xffffffffu, M, 1));
            float s = 0.f;
#pragma unroll
            for (int q = 0; q < 32; q++) s += __expf(x[q] - M);
            s += __shfl_xor_sync(0xffffffffu, s, 1);
            if (half == 0) {
                int grow = m0 + wr * 64 + i * 16 + r;
                int pcol = nt * 2 + wc;
                g_pmax[(size_t)grow * PCOLS + pcol] = M;
                g_psum[(size_t)grow * PCOLS + pcol] = s;
            }
            __syncwarp();
        }
    } else {
#pragma unroll
        for (int i = 0; i < 4; i++)
#pragma unroll
            for (int j = 0; j < 4; j++)
                wmma::store_matrix_sync(
                    &dst[(size_t)(m0 + wr * 64 + i * 16) * BDIM + n0 + wc * 64 + j * 16],
                    acc[i][j], BDIM, wmma::mem_row_major);
        if (bx != by) {
#pragma unroll
            for (int i = 0; i < 4; i++)
#pragma unroll
                for (int j = 0; j < 4; j++)
                    wmma::store_matrix_sync(
                        &dst[(size_t)(n0 + wc * 64 + j * 16) * BDIM + m0 + wr * 64 + i * 16],
                        acc[i][j], BDIM, wmma::mem_col_major);
        }
    }
}

// ======= fused per-row kernel: KD (2-pass KL, register rows, batched reductions)
//         + LSE combine + target dot + last-block finalize =======
// KL identity: kl = w/Zt + (Ms + ln Zs) - (Mt + ln Zt),
//   w = sum_j exp(b_j - Mt) * (b_j - a_j)
__global__ void __launch_bounds__(256) row_kernel(const int* __restrict__ epoch_p,
                                                  float* __restrict__ out, int out_size) {
    int row = blockIdx.x, tid = threadIdx.x;
    int li = g_labels[row];

    // --- pass 1: load sim/tsim as float4 into REGISTERS, scale, track maxes ---
    const float4* sr4 = (const float4*)(g_sim + (size_t)row * BDIM);
    const float4* tr4 = (const float4*)(g_tsim + (size_t)row * BDIM);
    const int4* lb4 = (const int4*)g_labels;
    float4 a[2], b[2];
    float ms = -CUDART_INF_F, mt = -CUDART_INF_F;
#pragma unroll
    for (int it = 0; it < 2; it++) {
        int j4 = it * 256 + tid;          // float4 index 0..511
        int4 lv = lb4[j4];
        a[it] = sr4[j4];
        b[it] = tr4[j4];
        float s0 = (lv.x == li) ? 0.25f : 0.125f;
        float s1 = (lv.y == li) ? 0.25f : 0.125f;
        float s2 = (lv.z == li) ? 0.25f : 0.125f;
        float s3 = (lv.w == li) ? 0.25f : 0.125f;
        a[it].x *= s0; a[it].y *= s1; a[it].z *= s2; a[it].w *= s3;
        b[it].x *= s0; b[it].y *= s1; b[it].z *= s2; b[it].w *= s3;
        ms = fmaxf(ms, fmaxf(fmaxf(a[it].x, a[it].y), fmaxf(a[it].z, a[it].w)));
        mt = fmaxf(mt, fmaxf(fmaxf(b[it].x, b[it].y), fmaxf(b[it].z, b[it].w)));
    }
    blkred_max2(ms, mt);
    float Ms = ms, Mt = mt;

    // --- pass 2 (registers): zs, zt, w + target dot, one batched reduction ---
    float zs = 0.f, zt = 0.f, wacc = 0.f;
#pragma unroll
    for (int it = 0; it < 2; it++) {
        zs += __expf(a[it].x - Ms) + __expf(a[it].y - Ms)
            + __expf(a[it].z - Ms) + __expf(a[it].w - Ms);
        float e0 = __expf(b[it].x - Mt), e1 = __expf(b[it].y - Mt);
        float e2 = __expf(b[it].z - Mt), e3 = __expf(b[it].w - Mt);
        zt += e0 + e1 + e2 + e3;
        wacc += e0 * (b[it].x - a[it].x) + e1 * (b[it].y - a[it].y)
              + e2 * (b[it].z - a[it].z) + e3 * (b[it].w - a[it].w);
    }
    const __nv_bfloat16* xv = g_xb + (size_t)row * EDIM;
    const __nv_bfloat16* wv = g_w + (size_t)li * EDIM;
    float d = 0.f;
    for (int i = tid; i < EDIM; i += 256)
        d += __bfloat162float(xv[i]) * __bfloat162float(wv[i]);

    blkred_sum4(zs, zt, wacc, d);
    float Zs = zs, Zt = zt, W = wacc;
    float tgt20 = d * 20.f;

    // --- LSE combine ---
    float pm = g_pmax[(size_t)row * PCOLS + tid];
    float pp = g_psum[(size_t)row * PCOLS + tid];
    float M = blkred(pm, 1);
    float S = blkred(pp * __expf(pm - M), 0);

    __shared__ int s_last;
    if (tid == 0) {
        g_kd_row[row] = W / Zt + (Ms + logf(Zs)) - (Mt + logf(Zt));
        g_rank_row[row] = logf(S) + M - tgt20;
        __threadfence();
        unsigned int prev = atomicAdd(&g_done, 1u);
        s_last = (prev == (unsigned int)(BDIM - 1)) ? 1 : 0;
    }
    __syncthreads();

    if (s_last) {
        __threadfence();
        float r = 0.f, k = 0.f;
        for (int i = tid; i < BDIM; i += 256) { r += g_rank_row[i]; k += g_kd_row[i]; }
        r = blkred(r, 0);
        k = blkred(k, 0);
        if (tid == 0) {
            float lr = r / (float)BDIM;
            float lk = k / (float)BDIM;
            int ei = *epoch_p;
            float ef = (ei >= 0 && ei < 10000000) ? (float)ei
                                                  : *reinterpret_cast<const float*>(epoch_p);
            float ramp = (ef / 150.f) * 16.0f;
            out[0] = lr + ramp * lk;
            if (out_size > 1) out[1] = lr;
            if (out_size > 2) out[2] = lk;
        }
    }
}

// ---------------- launch ----------------
extern "C" void kernel_launch(void* const* d_in, const int* in_sizes, int n_in,
                              void* d_out, int out_size) {
    const float* batch = (const float*)d_in[0];
    const float* teach = (const float*)d_in[1];
    const float* cmap  = (const float*)d_in[2];
    const void*  labels = d_in[3];
    const int*   epoch = (const int*)d_in[4];
    float* out = (float*)d_out;

    cudaFuncSetAttribute(fused_gemm_kernel,
                         cudaFuncAttributeMaxDynamicSharedMemorySize, DYNB);

    prep_kernel<<<NPREP_TOTAL, 128>>>(cmap, batch, teach, labels);
    fused_gemm_kernel<<<NLOGIT + 2 * NPAIR, 128, DYNB>>>();
    row_kernel<<<BDIM, 256>>>(epoch, out, out_size);
}